// round 7
// baseline (speedup 1.0000x reference)
#include <cuda_runtime.h>
#include <cuda_bf16.h>
#include <math.h>

// Problem constants (fixed by reference setup_inputs):
//   n = 100000 nodes, seq_len = 4, hidden = 128, n_edges = 1.6M
#define MAX_N      100000
#define MAX_EDGES  1600000
#define HIDDEN     128
#define SEQ_STRIDE (4 * 128)   // floats per node in semantics

#define TPB        256         // threads per fused block (8 warps)
#define NPB        32          // nodes per block tile

// Scratch (device globals; no allocations allowed).
__device__ int g_cnt[MAX_N];          // per-target edge counts (histogram)
__device__ int g_off[MAX_N + 1];      // CSR row offsets
__device__ int g_cursor[MAX_N];       // placement cursors (copy of offsets)
__device__ int g_srcs[MAX_EDGES];     // src indices sorted by tgt
__device__ int g_idx_is_64;           // 1 = int64 edge_index, 0 = int32

// ---------------------------------------------------------------------------
// f32x2 packed-FMA helpers (Blackwell fma.rn.f32x2 — 2 FMA per issue slot).
// ---------------------------------------------------------------------------
__device__ __forceinline__ unsigned long long pack_f32x2(float lo, float hi) {
    unsigned long long r;
    asm("mov.b64 %0, {%1, %2};" : "=l"(r) : "f"(lo), "f"(hi));
    return r;
}
__device__ __forceinline__ void fma_f32x2(unsigned long long& d,
                                          unsigned long long a,
                                          unsigned long long b) {
    asm("fma.rn.f32x2 %0, %1, %2, %0;" : "+l"(d) : "l"(a), "l"(b));
}
__device__ __forceinline__ float hsum_f32x2(unsigned long long v) {
    float lo, hi;
    asm("mov.b64 {%0, %1}, %2;" : "=f"(lo), "=f"(hi) : "l"(v));
    return lo + hi;
}

// ---------------------------------------------------------------------------
// Probe dtype (block 0, warp 0) + zero g_cnt (whole grid, grid-stride).
// ---------------------------------------------------------------------------
__global__ void probe_memset_kernel(const long long* __restrict__ ei64,
                                    long long n, int n_nodes) {
    int tid = blockIdx.x * blockDim.x + threadIdx.x;
    for (int i = tid; i < n_nodes; i += gridDim.x * blockDim.x) g_cnt[i] = 0;

    if (blockIdx.x == 0 && threadIdx.x < 32) {
        int lane = threadIdx.x;
        int bad = 0;
        #pragma unroll
        for (int i = 0; i < 8; i++) {
            long long v = ei64[lane * 8 + i];
            if (v < 0 || v >= n) bad = 1;
        }
        unsigned m = __ballot_sync(0xFFFFFFFFu, bad);
        if (lane == 0) g_idx_is_64 = (m == 0u) ? 1 : 0;
    }
}

// ---------------------------------------------------------------------------
// Histogram of targets (paired loads: one 16B/8B load per edge).
// ---------------------------------------------------------------------------
__global__ void hist_kernel(const void* __restrict__ ei_raw, int n_edges) {
    int e = blockIdx.x * blockDim.x + threadIdx.x;
    if (e >= n_edges) return;
    int tgt;
    if (g_idx_is_64) {
        longlong2 p = __ldg((const longlong2*)ei_raw + e);
        tgt = (int)p.y;
    } else {
        int2 p = __ldg((const int2*)ei_raw + e);
        tgt = p.y;
    }
    atomicAdd(&g_cnt[tgt], 1);
}

// ---------------------------------------------------------------------------
// Single-block exclusive scan over n counts -> g_off, g_cursor.
// ---------------------------------------------------------------------------
#define SCAN_THREADS 1024
__global__ void scan_kernel(int n) {
    __shared__ int ssum[SCAN_THREADS];
    int t = threadIdx.x;
    int chunk = (n + SCAN_THREADS - 1) / SCAN_THREADS;
    int lo = t * chunk;
    int hi = min(lo + chunk, n);

    int sum = 0;
    for (int i = lo; i < hi; i++) sum += g_cnt[i];
    ssum[t] = sum;
    __syncthreads();

    for (int off = 1; off < SCAN_THREADS; off <<= 1) {
        int v = (t >= off) ? ssum[t - off] : 0;
        __syncthreads();
        ssum[t] += v;
        __syncthreads();
    }

    int run = (t == 0) ? 0 : ssum[t - 1];
    for (int i = lo; i < hi; i++) {
        int c = g_cnt[i];
        g_off[i] = run;
        g_cursor[i] = run;
        run += c;
    }
    if (t == SCAN_THREADS - 1) g_off[n] = run;
}

// ---------------------------------------------------------------------------
// Placement: bucket src indices by target (counting-sort scatter).
// ---------------------------------------------------------------------------
__global__ void place_kernel(const void* __restrict__ ei_raw, int n_edges) {
    int e = blockIdx.x * blockDim.x + threadIdx.x;
    if (e >= n_edges) return;
    int src, tgt;
    if (g_idx_is_64) {
        longlong2 p = __ldg((const longlong2*)ei_raw + e);
        src = (int)p.x; tgt = (int)p.y;
    } else {
        int2 p = __ldg((const int2*)ei_raw + e);
        src = p.x; tgt = p.y;
    }
    int pos = atomicAdd(&g_cursor[tgt], 1);
    g_srcs[pos] = src;
}

// ---------------------------------------------------------------------------
// Fused kernel, one 32-node tile per block (grid 3125, 256 threads):
//  gather: warp w -> nodes 4w..4w+3; direct uniform CSR index loads,
//          8-wide unrolled float4 gathers (MLP 8), mean -> s[32][128].
//  gemm:   thread (tid>>5, tid&31) computes rows r0..r0+3 x cols c..c+3.
//          Per 2 k-steps: 2x LDG.128 of W rows (gmem, L1-hot), 4x broadcast
//          LDS.64 of s k-pairs, 16 FFMA2 with k-parity-packed accumulators.
//  epilogue: hsum, exact GELU, STG.128 per row.
// ---------------------------------------------------------------------------
__global__ void __launch_bounds__(TPB)
agg_gemm_gelu_kernel(const float* __restrict__ sem,
                     const float* __restrict__ W,
                     float* __restrict__ out,
                     int n) {
    __shared__ float s[NPB][HIDDEN];
    const int w    = threadIdx.x >> 5;
    const int lane = threadIdx.x & 31;
    const int base = blockIdx.x * NPB;

    // ---- Gather phase: warp w aggregates nodes base+4w .. base+4w+3 ----
    #pragma unroll
    for (int q = 0; q < 4; q++) {
        const int r    = w * 4 + q;
        const int node = base + r;
        float4 acc = make_float4(0.f, 0.f, 0.f, 0.f);
        float inv = 0.f;
        if (node < n) {
            const int beg = g_off[node];
            const int end = g_off[node + 1];
            inv = 1.0f / (float)max(end - beg, 1);
            int e = beg;
            for (; e + 8 <= end; e += 8) {
                int i0 = __ldg(g_srcs + e),     i1 = __ldg(g_srcs + e + 1);
                int i2 = __ldg(g_srcs + e + 2), i3 = __ldg(g_srcs + e + 3);
                int i4 = __ldg(g_srcs + e + 4), i5 = __ldg(g_srcs + e + 5);
                int i6 = __ldg(g_srcs + e + 6), i7 = __ldg(g_srcs + e + 7);
                float4 v0 = __ldg((const float4*)(sem + (size_t)i0 * SEQ_STRIDE) + lane);
                float4 v1 = __ldg((const float4*)(sem + (size_t)i1 * SEQ_STRIDE) + lane);
                float4 v2 = __ldg((const float4*)(sem + (size_t)i2 * SEQ_STRIDE) + lane);
                float4 v3 = __ldg((const float4*)(sem + (size_t)i3 * SEQ_STRIDE) + lane);
                float4 v4 = __ldg((const float4*)(sem + (size_t)i4 * SEQ_STRIDE) + lane);
                float4 v5 = __ldg((const float4*)(sem + (size_t)i5 * SEQ_STRIDE) + lane);
                float4 v6 = __ldg((const float4*)(sem + (size_t)i6 * SEQ_STRIDE) + lane);
                float4 v7 = __ldg((const float4*)(sem + (size_t)i7 * SEQ_STRIDE) + lane);
                acc.x += ((v0.x + v1.x) + (v2.x + v3.x)) + ((v4.x + v5.x) + (v6.x + v7.x));
                acc.y += ((v0.y + v1.y) + (v2.y + v3.y)) + ((v4.y + v5.y) + (v6.y + v7.y));
                acc.z += ((v0.z + v1.z) + (v2.z + v3.z)) + ((v4.z + v5.z) + (v6.z + v7.z));
                acc.w += ((v0.w + v1.w) + (v2.w + v3.w)) + ((v4.w + v5.w) + (v6.w + v7.w));
            }
            for (; e < end; e++) {
                int i0 = __ldg(g_srcs + e);
                float4 v0 = __ldg((const float4*)(sem + (size_t)i0 * SEQ_STRIDE) + lane);
                acc.x += v0.x; acc.y += v0.y; acc.z += v0.z; acc.w += v0.w;
            }
        }
        *(float4*)&s[r][lane * 4] =
            make_float4(acc.x * inv, acc.y * inv, acc.z * inv, acc.w * inv);
    }
    __syncthreads();

    // ---- GEMM phase: rows r0..r0+3 (broadcast within warp), cols c..c+3 ----
    const int r0 = (threadIdx.x >> 5) * 4;
    const int c  = (threadIdx.x & 31) * 4;

    // acc2[i][cc] packs (even-k partial, odd-k partial) for row r0+i, col c+cc.
    unsigned long long acc2[4][4];
    #pragma unroll
    for (int i = 0; i < 4; i++)
        #pragma unroll
        for (int cc = 0; cc < 4; cc++) acc2[i][cc] = 0ull;

    const float4* Wv = (const float4*)W;   // W[k][c..c+3] = Wv[k*32 + c/4]
    #pragma unroll 4
    for (int k = 0; k < HIDDEN; k += 2) {
        float4 wk  = __ldg(Wv + (size_t)k * 32 + (c >> 2));
        float4 wk1 = __ldg(Wv + (size_t)(k + 1) * 32 + (c >> 2));
        // k-pairs per column
        unsigned long long wp0 = pack_f32x2(wk.x, wk1.x);
        unsigned long long wp1 = pack_f32x2(wk.y, wk1.y);
        unsigned long long wp2 = pack_f32x2(wk.z, wk1.z);
        unsigned long long wp3 = pack_f32x2(wk.w, wk1.w);
        #pragma unroll
        for (int i = 0; i < 4; i++) {
            // (s[r][k], s[r][k+1]) — 8B-aligned broadcast LDS.64
            unsigned long long s2 = *(const unsigned long long*)&s[r0 + i][k];
            fma_f32x2(acc2[i][0], s2, wp0);
            fma_f32x2(acc2[i][1], s2, wp1);
            fma_f32x2(acc2[i][2], s2, wp2);
            fma_f32x2(acc2[i][3], s2, wp3);
        }
    }

    // ---- Epilogue: hsum, exact GELU, vector store ----
    #pragma unroll
    for (int i = 0; i < 4; i++) {
        int row = base + r0 + i;
        if (row < n) {
            float4 o;
            o.x = hsum_f32x2(acc2[i][0]);
            o.y = hsum_f32x2(acc2[i][1]);
            o.z = hsum_f32x2(acc2[i][2]);
            o.w = hsum_f32x2(acc2[i][3]);
            // exact GELU: 0.5*x*(1 + erf(x/sqrt(2)))
            o.x = 0.5f * o.x * (1.0f + erff(o.x * 0.70710678118654752f));
            o.y = 0.5f * o.y * (1.0f + erff(o.y * 0.70710678118654752f));
            o.z = 0.5f * o.z * (1.0f + erff(o.z * 0.70710678118654752f));
            o.w = 0.5f * o.w * (1.0f + erff(o.w * 0.70710678118654752f));
            *(float4*)(out + (size_t)row * HIDDEN + c) = o;
        }
    }
}

// ---------------------------------------------------------------------------
// kernel_launch: probe+memset -> hist -> scan -> place -> fused.
// All async on the default stream; graph-capturable; no allocations.
// Input order (metadata): semantics, attention_masks (unused), W, edge_index.
// ---------------------------------------------------------------------------
extern "C" void kernel_launch(void* const* d_in, const int* in_sizes, int n_in,
                              void* d_out, int out_size) {
    const float* sem = (const float*)d_in[0];
    const float* W   = (const float*)d_in[2];
    const void*  ei  = d_in[3];
    float* out = (float*)d_out;

    const int n       = in_sizes[0] / SEQ_STRIDE;   // 100000
    const int n_edges = in_sizes[3] / 2;            // 1600000

    probe_memset_kernel<<<200, 512>>>((const long long*)ei, (long long)n, n);

    int eb = (n_edges + 511) / 512;
    hist_kernel<<<eb, 512>>>(ei, n_edges);
    scan_kernel<<<1, SCAN_THREADS>>>(n);
    place_kernel<<<eb, 512>>>(ei, n_edges);

    int blocks = (n + NPB - 1) / NPB;
    agg_gemm_gelu_kernel<<<blocks, TPB>>>(sem, W, out, n);
}

// round 8
// speedup vs baseline: 1.1174x; 1.1174x over previous
#include <cuda_runtime.h>
#include <cuda_bf16.h>
#include <math.h>

// Problem constants (fixed by reference setup_inputs):
//   n = 100000 nodes, seq_len = 4, hidden = 128, n_edges = 1.6M
#define MAX_N      100000
#define MAX_EDGES  1600000
#define HIDDEN     128
#define SEQ_STRIDE (4 * 128)   // floats per node in semantics

// Scratch (device globals; no allocations allowed).
__device__ float g_sums[MAX_N * HIDDEN];   // 51.2 MB accumulators
__device__ float g_cntf[MAX_N];            // per-target in-degree (float)
__device__ int   g_cnt_src[MAX_N];         // per-source out-degree (histogram)
__device__ int   g_off[MAX_N + 1];         // CSR-by-source offsets
__device__ int   g_cursor[MAX_N];          // placement cursors
__device__ int   g_tgts[MAX_EDGES];        // target ids sorted by source
__device__ int   g_idx_is_64;              // 1 = int64 edge_index, 0 = int32

// ---------------------------------------------------------------------------
// Probe: decide whether edge_index is genuine int64 or packed int32 pairs.
// ---------------------------------------------------------------------------
__global__ void probe_dtype_kernel(const long long* __restrict__ ei64,
                                   long long n) {
    int lane = threadIdx.x;
    int bad = 0;
    #pragma unroll
    for (int i = 0; i < 8; i++) {
        long long v = ei64[lane * 8 + i];
        if (v < 0 || v >= n) bad = 1;
    }
    unsigned m = __ballot_sync(0xFFFFFFFFu, bad);
    if (lane == 0) g_idx_is_64 = (m == 0u) ? 1 : 0;
}

// ---------------------------------------------------------------------------
// Histogram: out-degree per source (int, for CSR) and in-degree per target
// (float, used directly as the mean divisor later).
// ---------------------------------------------------------------------------
__global__ void hist_kernel(const void* __restrict__ ei_raw, int n_edges) {
    int e = blockIdx.x * blockDim.x + threadIdx.x;
    if (e >= n_edges) return;
    int src, tgt;
    if (g_idx_is_64) {
        longlong2 p = __ldg((const longlong2*)ei_raw + e);
        src = (int)p.x; tgt = (int)p.y;
    } else {
        int2 p = __ldg((const int2*)ei_raw + e);
        src = p.x; tgt = p.y;
    }
    atomicAdd(&g_cnt_src[src], 1);
    atomicAdd(&g_cntf[tgt], 1.0f);
}

// ---------------------------------------------------------------------------
// Single-block exclusive scan over source counts -> g_off, g_cursor.
// ---------------------------------------------------------------------------
#define SCAN_THREADS 1024
__global__ void scan_kernel(int n) {
    __shared__ int ssum[SCAN_THREADS];
    int t = threadIdx.x;
    int chunk = (n + SCAN_THREADS - 1) / SCAN_THREADS;
    int lo = t * chunk;
    int hi = min(lo + chunk, n);

    int sum = 0;
    for (int i = lo; i < hi; i++) sum += g_cnt_src[i];
    ssum[t] = sum;
    __syncthreads();

    for (int off = 1; off < SCAN_THREADS; off <<= 1) {
        int v = (t >= off) ? ssum[t - off] : 0;
        __syncthreads();
        ssum[t] += v;
        __syncthreads();
    }

    int run = (t == 0) ? 0 : ssum[t - 1];
    for (int i = lo; i < hi; i++) {
        int c = g_cnt_src[i];
        g_off[i] = run;
        g_cursor[i] = run;
        run += c;
    }
    if (t == SCAN_THREADS - 1) g_off[n] = run;
}

// ---------------------------------------------------------------------------
// Placement: bucket TARGET ids by SOURCE (counting sort on src).
// ---------------------------------------------------------------------------
__global__ void place_kernel(const void* __restrict__ ei_raw, int n_edges) {
    int e = blockIdx.x * blockDim.x + threadIdx.x;
    if (e >= n_edges) return;
    int src, tgt;
    if (g_idx_is_64) {
        longlong2 p = __ldg((const longlong2*)ei_raw + e);
        src = (int)p.x; tgt = (int)p.y;
    } else {
        int2 p = __ldg((const int2*)ei_raw + e);
        src = p.x; tgt = p.y;
    }
    int pos = atomicAdd(&g_cursor[src], 1);
    g_tgts[pos] = tgt;
}

// ---------------------------------------------------------------------------
// Scatter (the big win): one warp per SOURCE node. Load the 512 B source row
// ONCE into registers, then for each outgoing edge issue one fire-and-forget
// red.global.add.v4.f32 into g_sums[tgt]. Reads: 51 MB total (was 819 MB).
// ---------------------------------------------------------------------------
__global__ void scatter_by_src_kernel(const float* __restrict__ sem, int n) {
    int warp = (blockIdx.x * blockDim.x + threadIdx.x) >> 5;
    int lane = threadIdx.x & 31;
    if (warp >= n) return;

    const int beg = g_off[warp];
    const int end = g_off[warp + 1];
    if (beg == end) return;

    // Source row, one float4 per lane (512 B per warp), loaded once.
    const float4 v = __ldg((const float4*)(sem + (size_t)warp * SEQ_STRIDE) + lane);

    int e = beg;
    // 4-wide unroll: pipeline target-id loads ahead of REDs.
    for (; e + 4 <= end; e += 4) {
        int t0 = __ldg(g_tgts + e);
        int t1 = __ldg(g_tgts + e + 1);
        int t2 = __ldg(g_tgts + e + 2);
        int t3 = __ldg(g_tgts + e + 3);
        float* d0 = g_sums + (size_t)t0 * HIDDEN + lane * 4;
        float* d1 = g_sums + (size_t)t1 * HIDDEN + lane * 4;
        float* d2 = g_sums + (size_t)t2 * HIDDEN + lane * 4;
        float* d3 = g_sums + (size_t)t3 * HIDDEN + lane * 4;
        asm volatile("red.global.add.v4.f32 [%0], {%1, %2, %3, %4};"
                     :: "l"(d0), "f"(v.x), "f"(v.y), "f"(v.z), "f"(v.w) : "memory");
        asm volatile("red.global.add.v4.f32 [%0], {%1, %2, %3, %4};"
                     :: "l"(d1), "f"(v.x), "f"(v.y), "f"(v.z), "f"(v.w) : "memory");
        asm volatile("red.global.add.v4.f32 [%0], {%1, %2, %3, %4};"
                     :: "l"(d2), "f"(v.x), "f"(v.y), "f"(v.z), "f"(v.w) : "memory");
        asm volatile("red.global.add.v4.f32 [%0], {%1, %2, %3, %4};"
                     :: "l"(d3), "f"(v.x), "f"(v.y), "f"(v.z), "f"(v.w) : "memory");
    }
    for (; e < end; e++) {
        int t0 = __ldg(g_tgts + e);
        float* d0 = g_sums + (size_t)t0 * HIDDEN + lane * 4;
        asm volatile("red.global.add.v4.f32 [%0], {%1, %2, %3, %4};"
                     :: "l"(d0), "f"(v.x), "f"(v.y), "f"(v.z), "f"(v.w) : "memory");
    }
}

// ---------------------------------------------------------------------------
// Final: fused (sums @ W) / max(cnt,1) -> exact GELU -> out.
// (Verbatim round-2 kernel — known good.)
// ---------------------------------------------------------------------------
#define RPB 8
__global__ void gemm_mean_gelu_kernel(const float* __restrict__ W,
                                      float* __restrict__ out,
                                      int n) {
    __shared__ float s[RPB][HIDDEN];
    const int r0 = blockIdx.x * RPB;
    const int j  = threadIdx.x;   // 0..127

    #pragma unroll
    for (int r = 0; r < RPB; r++) {
        int row = r0 + r;
        s[r][j] = (row < n) ? g_sums[(size_t)row * HIDDEN + j] : 0.0f;
    }
    __syncthreads();

    float acc[RPB];
    #pragma unroll
    for (int r = 0; r < RPB; r++) acc[r] = 0.0f;

    #pragma unroll 4
    for (int k = 0; k < HIDDEN; k++) {
        float w = __ldg(W + k * HIDDEN + j);
        #pragma unroll
        for (int r = 0; r < RPB; r++) acc[r] = fmaf(s[r][k], w, acc[r]);
    }

    #pragma unroll
    for (int r = 0; r < RPB; r++) {
        int row = r0 + r;
        if (row < n) {
            float c = g_cntf[row];
            float m = acc[r] / fmaxf(c, 1.0f);
            // exact GELU: 0.5*x*(1 + erf(x/sqrt(2)))
            out[(size_t)row * HIDDEN + j] =
                0.5f * m * (1.0f + erff(m * 0.70710678118654752f));
        }
    }
}

// ---------------------------------------------------------------------------
// kernel_launch: probe -> memsets -> hist -> scan -> place -> scatter -> gemm.
// All async on the default stream; graph-capturable; no allocations.
// Input order (metadata): semantics, attention_masks (unused), W, edge_index.
// ---------------------------------------------------------------------------
extern "C" void kernel_launch(void* const* d_in, const int* in_sizes, int n_in,
                              void* d_out, int out_size) {
    const float* sem = (const float*)d_in[0];
    const float* W   = (const float*)d_in[2];
    const void*  ei  = d_in[3];
    float* out = (float*)d_out;

    const int n       = in_sizes[0] / SEQ_STRIDE;   // 100000
    const int n_edges = in_sizes[3] / 2;            // 1600000

    void *sums_ptr = nullptr, *cntf_ptr = nullptr, *csrc_ptr = nullptr;
    cudaGetSymbolAddress(&sums_ptr, g_sums);
    cudaGetSymbolAddress(&cntf_ptr, g_cntf);
    cudaGetSymbolAddress(&csrc_ptr, g_cnt_src);

    probe_dtype_kernel<<<1, 32>>>((const long long*)ei, (long long)n);

    cudaMemsetAsync(sums_ptr, 0, (size_t)n * HIDDEN * sizeof(float));
    cudaMemsetAsync(cntf_ptr, 0, (size_t)n * sizeof(float));
    cudaMemsetAsync(csrc_ptr, 0, (size_t)n * sizeof(int));

    int eb = (n_edges + 511) / 512;
    hist_kernel<<<eb, 512>>>(ei, n_edges);
    scan_kernel<<<1, SCAN_THREADS>>>(n);
    place_kernel<<<eb, 512>>>(ei, n_edges);

    // one warp per source node, 8 warps per 256-thread block
    int sb = (n + 7) / 8;
    scatter_by_src_kernel<<<sb, 256>>>(sem, n);

    int gb = (n + RPB - 1) / RPB;
    gemm_mean_gelu_kernel<<<gb, HIDDEN>>>(W, out, n);
}

// round 9
// speedup vs baseline: 1.3663x; 1.2227x over previous
#include <cuda_runtime.h>
#include <cuda_bf16.h>
#include <math.h>

// Problem constants (fixed by reference setup_inputs):
//   n = 100000 nodes, seq_len = 4, hidden = 128, n_edges = 1.6M
#define MAX_N      100000
#define MAX_EDGES  1600000
#define HIDDEN     128
#define SEQ_STRIDE (4 * 128)   // floats per node in semantics

#define TPB        256         // threads per fused block (8 warps)
#define NPB        64          // nodes (rows) per block tile

// Scratch (device globals; no allocations allowed).
__device__ int g_cnt[MAX_N];          // per-target in-degree (histogram)
__device__ int g_off[MAX_N + 1];      // CSR-by-target offsets
__device__ int g_cursor[MAX_N];       // placement cursors
__device__ int g_srcs[MAX_EDGES];     // source ids sorted by target
__device__ int g_idx_is_64;           // 1 = int64 edge_index, 0 = int32

// ---------------------------------------------------------------------------
// f32x2 packed-FMA helpers (Blackwell fma.rn.f32x2 — 2 FMA per issue slot).
// ---------------------------------------------------------------------------
__device__ __forceinline__ unsigned long long pack_dup_f32x2(float v) {
    unsigned long long r;
    asm("mov.b64 %0, {%1, %1};" : "=l"(r) : "f"(v));
    return r;
}
__device__ __forceinline__ void fma_f32x2(unsigned long long& d,
                                          unsigned long long a,
                                          unsigned long long b) {
    asm("fma.rn.f32x2 %0, %1, %2, %0;" : "+l"(d) : "l"(a), "l"(b));
}
__device__ __forceinline__ void unpack_f32x2(unsigned long long v,
                                             float& lo, float& hi) {
    asm("mov.b64 {%0, %1}, %2;" : "=f"(lo), "=f"(hi) : "l"(v));
}

// ---------------------------------------------------------------------------
// Probe dtype (block 0, warp 0) + zero g_cnt (whole grid, grid-stride).
// ---------------------------------------------------------------------------
__global__ void probe_memset_kernel(const long long* __restrict__ ei64,
                                    long long n, int n_nodes) {
    int tid = blockIdx.x * blockDim.x + threadIdx.x;
    for (int i = tid; i < n_nodes; i += gridDim.x * blockDim.x) g_cnt[i] = 0;

    if (blockIdx.x == 0 && threadIdx.x < 32) {
        int lane = threadIdx.x;
        int bad = 0;
        #pragma unroll
        for (int i = 0; i < 8; i++) {
            long long v = ei64[lane * 8 + i];
            if (v < 0 || v >= n) bad = 1;
        }
        unsigned m = __ballot_sync(0xFFFFFFFFu, bad);
        if (lane == 0) g_idx_is_64 = (m == 0u) ? 1 : 0;
    }
}

// ---------------------------------------------------------------------------
// Histogram of TARGET in-degree.
// ---------------------------------------------------------------------------
__global__ void hist_kernel(const void* __restrict__ ei_raw, int n_edges) {
    int e = blockIdx.x * blockDim.x + threadIdx.x;
    if (e >= n_edges) return;
    int tgt;
    if (g_idx_is_64) {
        longlong2 p = __ldg((const longlong2*)ei_raw + e);
        tgt = (int)p.y;
    } else {
        int2 p = __ldg((const int2*)ei_raw + e);
        tgt = p.y;
    }
    atomicAdd(&g_cnt[tgt], 1);
}

// ---------------------------------------------------------------------------
// Single-block exclusive scan over counts -> g_off, g_cursor.
// ---------------------------------------------------------------------------
#define SCAN_THREADS 1024
__global__ void scan_kernel(int n) {
    __shared__ int ssum[SCAN_THREADS];
    int t = threadIdx.x;
    int chunk = (n + SCAN_THREADS - 1) / SCAN_THREADS;
    int lo = t * chunk;
    int hi = min(lo + chunk, n);

    int sum = 0;
    for (int i = lo; i < hi; i++) sum += g_cnt[i];
    ssum[t] = sum;
    __syncthreads();

    for (int off = 1; off < SCAN_THREADS; off <<= 1) {
        int v = (t >= off) ? ssum[t - off] : 0;
        __syncthreads();
        ssum[t] += v;
        __syncthreads();
    }

    int run = (t == 0) ? 0 : ssum[t - 1];
    for (int i = lo; i < hi; i++) {
        int c = g_cnt[i];
        g_off[i] = run;
        g_cursor[i] = run;
        run += c;
    }
    if (t == SCAN_THREADS - 1) g_off[n] = run;
}

// ---------------------------------------------------------------------------
// Placement: bucket SOURCE ids by TARGET (counting sort on tgt).
// ---------------------------------------------------------------------------
__global__ void place_kernel(const void* __restrict__ ei_raw, int n_edges) {
    int e = blockIdx.x * blockDim.x + threadIdx.x;
    if (e >= n_edges) return;
    int src, tgt;
    if (g_idx_is_64) {
        longlong2 p = __ldg((const longlong2*)ei_raw + e);
        src = (int)p.x; tgt = (int)p.y;
    } else {
        int2 p = __ldg((const int2*)ei_raw + e);
        src = p.x; tgt = p.y;
    }
    int pos = atomicAdd(&g_cursor[tgt], 1);
    g_srcs[pos] = src;
}

// ---------------------------------------------------------------------------
// Fused gather + GEMM + GELU. 64 nodes per block, 256 threads, 96 KB smem.
//
// smem layout (dynamic):
//   sB[128][128]  : W staged row-major (reads are warp-uniform -> broadcast)
//   sA[128][64]   : mean rows, k-major, XOR-(k>>2) swizzled on the m index:
//                   element (k,m) lives at sA[k*64 + (m ^ (k>>2))].
//                   * gather write: lane l writes k=4l..4l+3 -> k>>2 = l,
//                     bank = (m ^ l) & 31  -> conflict-free across lanes.
//                   * gemm read: fixed k, m = lane -> lane ^ const -> perm,
//                     conflict-free.
//
// GEMM mapping: warp w owns columns n0=16w..16w+15 for ALL 64 rows.
//   thread: rows m=lane and m=lane+32, 8 n-pairs as f32x2 accumulators.
//   per k: 2 LDS.32 (A) + 2 dup-movs + 8 uniform LDS.64 (W pairs) + 16 FFMA2.
// ---------------------------------------------------------------------------
extern __shared__ float dsm[];

__global__ void __launch_bounds__(TPB)
agg_gemm_gelu_kernel(const float* __restrict__ sem,
                     const float* __restrict__ W,
                     float* __restrict__ out,
                     int n) {
    float* sB = dsm;                    // [128*128]
    float* sA = dsm + HIDDEN * HIDDEN;  // [128*64] swizzled

    const int w    = threadIdx.x >> 5;
    const int lane = threadIdx.x & 31;
    const int base = blockIdx.x * NPB;

    // ---- Stage W (coalesced float4; issues early, overlaps gather) ----
    {
        const float4* Wv = (const float4*)W;
        float4* sBv = (float4*)sB;
        #pragma unroll
        for (int i = 0; i < (HIDDEN * HIDDEN / 4) / TPB; i++)
            sBv[threadIdx.x + i * TPB] = __ldg(Wv + threadIdx.x + i * TPB);
    }

    // ---- Gather phase: warp w aggregates nodes base + w, w+8, ..., w+56 ----
    for (int q = 0; q < NPB / 8; q++) {
        const int r    = q * 8 + w;       // local row 0..63
        const int node = base + r;
        float4 acc = make_float4(0.f, 0.f, 0.f, 0.f);
        float inv = 0.f;
        if (node < n) {
            const int beg = g_off[node];
            const int end = g_off[node + 1];
            inv = 1.0f / (float)max(end - beg, 1);
            int e = beg;
            for (; e + 8 <= end; e += 8) {
                int i0 = __ldg(g_srcs + e),     i1 = __ldg(g_srcs + e + 1);
                int i2 = __ldg(g_srcs + e + 2), i3 = __ldg(g_srcs + e + 3);
                int i4 = __ldg(g_srcs + e + 4), i5 = __ldg(g_srcs + e + 5);
                int i6 = __ldg(g_srcs + e + 6), i7 = __ldg(g_srcs + e + 7);
                float4 v0 = __ldg((const float4*)(sem + (size_t)i0 * SEQ_STRIDE) + lane);
                float4 v1 = __ldg((const float4*)(sem + (size_t)i1 * SEQ_STRIDE) + lane);
                float4 v2 = __ldg((const float4*)(sem + (size_t)i2 * SEQ_STRIDE) + lane);
                float4 v3 = __ldg((const float4*)(sem + (size_t)i3 * SEQ_STRIDE) + lane);
                float4 v4 = __ldg((const float4*)(sem + (size_t)i4 * SEQ_STRIDE) + lane);
                float4 v5 = __ldg((const float4*)(sem + (size_t)i5 * SEQ_STRIDE) + lane);
                float4 v6 = __ldg((const float4*)(sem + (size_t)i6 * SEQ_STRIDE) + lane);
                float4 v7 = __ldg((const float4*)(sem + (size_t)i7 * SEQ_STRIDE) + lane);
                acc.x += ((v0.x + v1.x) + (v2.x + v3.x)) + ((v4.x + v5.x) + (v6.x + v7.x));
                acc.y += ((v0.y + v1.y) + (v2.y + v3.y)) + ((v4.y + v5.y) + (v6.y + v7.y));
                acc.z += ((v0.z + v1.z) + (v2.z + v3.z)) + ((v4.z + v5.z) + (v6.z + v7.z));
                acc.w += ((v0.w + v1.w) + (v2.w + v3.w)) + ((v4.w + v5.w) + (v6.w + v7.w));
            }
            for (; e < end; e++) {
                int i0 = __ldg(g_srcs + e);
                float4 v0 = __ldg((const float4*)(sem + (size_t)i0 * SEQ_STRIDE) + lane);
                acc.x += v0.x; acc.y += v0.y; acc.z += v0.z; acc.w += v0.w;
            }
        }
        // Transposed, swizzled store; k = 4*lane + i, k>>2 = lane.
        const int ms = r ^ lane;          // swizzled m index (r<64, lane<32)
        sA[(4 * lane + 0) * NPB + ms] = acc.x * inv;
        sA[(4 * lane + 1) * NPB + ms] = acc.y * inv;
        sA[(4 * lane + 2) * NPB + ms] = acc.z * inv;
        sA[(4 * lane + 3) * NPB + ms] = acc.w * inv;
    }
    __syncthreads();

    // ---- GEMM phase ----
    const int n0 = w * 16;
    unsigned long long acc2[2][8];
    #pragma unroll
    for (int mi = 0; mi < 2; mi++)
        #pragma unroll
        for (int j = 0; j < 8; j++) acc2[mi][j] = 0ull;

    #pragma unroll 4
    for (int k = 0; k < HIDDEN; k++) {
        const int aoff = k * NPB + ((lane ^ (k >> 2)) & 63);
        unsigned long long a0 = pack_dup_f32x2(sA[aoff]);
        unsigned long long a1 = pack_dup_f32x2(sA[aoff + 32]);
        const unsigned long long* brow =
            (const unsigned long long*)(sB + k * HIDDEN + n0);
        #pragma unroll
        for (int j = 0; j < 8; j++) {
            unsigned long long b2 = brow[j];   // warp-uniform LDS.64
            fma_f32x2(acc2[0][j], a0, b2);
            fma_f32x2(acc2[1][j], a1, b2);
        }
    }

    // ---- Epilogue: exact GELU + vector stores ----
    #pragma unroll
    for (int mi = 0; mi < 2; mi++) {
        int row = base + lane + 32 * mi;
        if (row < n) {
            float* orow = out + (size_t)row * HIDDEN + n0;
            #pragma unroll
            for (int jj = 0; jj < 4; jj++) {
                float4 o;
                unpack_f32x2(acc2[mi][2 * jj],     o.x, o.y);
                unpack_f32x2(acc2[mi][2 * jj + 1], o.z, o.w);
                o.x = 0.5f * o.x * (1.0f + erff(o.x * 0.70710678118654752f));
                o.y = 0.5f * o.y * (1.0f + erff(o.y * 0.70710678118654752f));
                o.z = 0.5f * o.z * (1.0f + erff(o.z * 0.70710678118654752f));
                o.w = 0.5f * o.w * (1.0f + erff(o.w * 0.70710678118654752f));
                *(float4*)(orow + 4 * jj) = o;
            }
        }
    }
}

// ---------------------------------------------------------------------------
// kernel_launch: probe+memset -> hist -> scan -> place -> fused.
// All async on the default stream; graph-capturable; no allocations.
// Input order (metadata): semantics, attention_masks (unused), W, edge_index.
// ---------------------------------------------------------------------------
extern "C" void kernel_launch(void* const* d_in, const int* in_sizes, int n_in,
                              void* d_out, int out_size) {
    const float* sem = (const float*)d_in[0];
    const float* W   = (const float*)d_in[2];
    const void*  ei  = d_in[3];
    float* out = (float*)d_out;

    const int n       = in_sizes[0] / SEQ_STRIDE;   // 100000
    const int n_edges = in_sizes[3] / 2;            // 1600000

    probe_memset_kernel<<<200, 512>>>((const long long*)ei, (long long)n, n);

    int eb = (n_edges + 511) / 512;
    hist_kernel<<<eb, 512>>>(ei, n_edges);
    scan_kernel<<<1, SCAN_THREADS>>>(n);
    place_kernel<<<eb, 512>>>(ei, n_edges);

    const int smem_bytes = (HIDDEN * HIDDEN + HIDDEN * NPB) * (int)sizeof(float);
    cudaFuncSetAttribute(agg_gemm_gelu_kernel,
                         cudaFuncAttributeMaxDynamicSharedMemorySize,
                         smem_bytes);
    int blocks = (n + NPB - 1) / NPB;
    agg_gemm_gelu_kernel<<<blocks, TPB, smem_bytes>>>(sem, W, out, n);
}

// round 10
// speedup vs baseline: 1.4287x; 1.0456x over previous
#include <cuda_runtime.h>
#include <cuda_fp16.h>
#include <math.h>

// Problem constants (fixed by reference setup_inputs):
//   n = 100000 nodes, seq_len = 4, hidden = 128, n_edges = 1.6M
#define MAX_N      100000
#define MAX_EDGES  1600000
#define HIDDEN     128
#define SEQ_STRIDE (4 * 128)   // floats per node in semantics

#define TPB        256         // threads per fused block (8 warps)
#define NPB        64          // nodes (rows) per block tile

// Scratch (device globals; no allocations allowed).
__device__ __half g_sem16[MAX_N * HIDDEN]; // fp16 copy of sem[:,0,:] (25.6 MB)
__device__ int g_cnt[MAX_N];          // per-target in-degree (histogram)
__device__ int g_off[MAX_N + 1];      // CSR-by-target offsets
__device__ int g_cursor[MAX_N];       // placement cursors
__device__ int g_srcs[MAX_EDGES];     // source ids sorted by target
__device__ int g_idx_is_64;           // 1 = int64 edge_index, 0 = int32

// ---------------------------------------------------------------------------
// f32x2 packed-FMA helpers (Blackwell fma.rn.f32x2 — 2 FMA per issue slot).
// ---------------------------------------------------------------------------
__device__ __forceinline__ unsigned long long pack_dup_f32x2(float v) {
    unsigned long long r;
    asm("mov.b64 %0, {%1, %1};" : "=l"(r) : "f"(v));
    return r;
}
__device__ __forceinline__ void fma_f32x2(unsigned long long& d,
                                          unsigned long long a,
                                          unsigned long long b) {
    asm("fma.rn.f32x2 %0, %1, %2, %0;" : "+l"(d) : "l"(a), "l"(b));
}
__device__ __forceinline__ void unpack_f32x2(unsigned long long v,
                                             float& lo, float& hi) {
    asm("mov.b64 {%0, %1}, %2;" : "=f"(lo), "=f"(hi) : "l"(v));
}

// ---------------------------------------------------------------------------
// Prep: dtype probe (block 0 warp 0) + zero g_cnt + convert sem[:,0,:] to
// fp16 (grid-stride; each thread converts 8 floats -> 8 halfs).
// ---------------------------------------------------------------------------
__global__ void prep_kernel(const float* __restrict__ sem,
                            const long long* __restrict__ ei64,
                            long long n, int n_nodes) {
    int tid = blockIdx.x * blockDim.x + threadIdx.x;
    int nt  = gridDim.x * blockDim.x;

    for (int i = tid; i < n_nodes; i += nt) g_cnt[i] = 0;

    // 12.8M halfs, 8 per thread.
    const int n_oct = n_nodes * (HIDDEN / 8);
    for (int i = tid; i < n_oct; i += nt) {
        int node = i >> 4;           // 16 octs per node
        int oct  = i & 15;
        const float4* src = (const float4*)(sem + (size_t)node * SEQ_STRIDE + oct * 8);
        float4 a = __ldg(src);
        float4 b = __ldg(src + 1);
        __half2 h[4];
        h[0] = __floats2half2_rn(a.x, a.y);
        h[1] = __floats2half2_rn(a.z, a.w);
        h[2] = __floats2half2_rn(b.x, b.y);
        h[3] = __floats2half2_rn(b.z, b.w);
        *(uint4*)(g_sem16 + (size_t)node * HIDDEN + oct * 8) = *(uint4*)h;
    }

    if (blockIdx.x == 0 && threadIdx.x < 32) {
        int lane = threadIdx.x;
        int bad = 0;
        #pragma unroll
        for (int i = 0; i < 8; i++) {
            long long v = ei64[lane * 8 + i];
            if (v < 0 || v >= n) bad = 1;
        }
        unsigned m = __ballot_sync(0xFFFFFFFFu, bad);
        if (lane == 0) g_idx_is_64 = (m == 0u) ? 1 : 0;
    }
}

// ---------------------------------------------------------------------------
// Histogram of TARGET in-degree.
// ---------------------------------------------------------------------------
__global__ void hist_kernel(const void* __restrict__ ei_raw, int n_edges) {
    int e = blockIdx.x * blockDim.x + threadIdx.x;
    if (e >= n_edges) return;
    int tgt;
    if (g_idx_is_64) {
        longlong2 p = __ldg((const longlong2*)ei_raw + e);
        tgt = (int)p.y;
    } else {
        int2 p = __ldg((const int2*)ei_raw + e);
        tgt = p.y;
    }
    atomicAdd(&g_cnt[tgt], 1);
}

// ---------------------------------------------------------------------------
// Single-block exclusive scan over counts -> g_off, g_cursor.
// ---------------------------------------------------------------------------
#define SCAN_THREADS 1024
__global__ void scan_kernel(int n) {
    __shared__ int ssum[SCAN_THREADS];
    int t = threadIdx.x;
    int chunk = (n + SCAN_THREADS - 1) / SCAN_THREADS;
    int lo = t * chunk;
    int hi = min(lo + chunk, n);

    int sum = 0;
    for (int i = lo; i < hi; i++) sum += g_cnt[i];
    ssum[t] = sum;
    __syncthreads();

    for (int off = 1; off < SCAN_THREADS; off <<= 1) {
        int v = (t >= off) ? ssum[t - off] : 0;
        __syncthreads();
        ssum[t] += v;
        __syncthreads();
    }

    int run = (t == 0) ? 0 : ssum[t - 1];
    for (int i = lo; i < hi; i++) {
        int c = g_cnt[i];
        g_off[i] = run;
        g_cursor[i] = run;
        run += c;
    }
    if (t == SCAN_THREADS - 1) g_off[n] = run;
}

// ---------------------------------------------------------------------------
// Placement: bucket SOURCE ids by TARGET (counting sort on tgt).
// ---------------------------------------------------------------------------
__global__ void place_kernel(const void* __restrict__ ei_raw, int n_edges) {
    int e = blockIdx.x * blockDim.x + threadIdx.x;
    if (e >= n_edges) return;
    int src, tgt;
    if (g_idx_is_64) {
        longlong2 p = __ldg((const longlong2*)ei_raw + e);
        src = (int)p.x; tgt = (int)p.y;
    } else {
        int2 p = __ldg((const int2*)ei_raw + e);
        src = p.x; tgt = p.y;
    }
    int pos = atomicAdd(&g_cursor[tgt], 1);
    g_srcs[pos] = tgt >= 0 ? src : src;   // keep simple; src
}

// ---------------------------------------------------------------------------
// Fused gather(fp16) + GEMM(fp32) + GELU. 64 nodes/block, 256 thr, 96 KB smem.
// Gather: warp per node (8 nodes/warp), each edge = one warp-LDG.64 (256 B),
//         half2 -> float accumulate, mean, swizzled transpose into sA.
// GEMM  : round-9 verified mapping (warp owns 16 cols x 64 rows, f32x2).
// ---------------------------------------------------------------------------
extern __shared__ float dsm[];

__global__ void __launch_bounds__(TPB)
agg_gemm_gelu_kernel(const float* __restrict__ W,
                     float* __restrict__ out,
                     int n) {
    float* sB = dsm;                    // [128*128] W row-major
    float* sA = dsm + HIDDEN * HIDDEN;  // [128*64] k-major, m ^ (k>>2) swizzle

    const int w    = threadIdx.x >> 5;
    const int lane = threadIdx.x & 31;
    const int base = blockIdx.x * NPB;

    // ---- Stage W ----
    {
        const float4* Wv = (const float4*)W;
        float4* sBv = (float4*)sB;
        #pragma unroll
        for (int i = 0; i < (HIDDEN * HIDDEN / 4) / TPB; i++)
            sBv[threadIdx.x + i * TPB] = __ldg(Wv + threadIdx.x + i * TPB);
    }

    // ---- Gather phase (fp16 rows): lane covers halfs 4*lane .. 4*lane+3 ----
    for (int q = 0; q < NPB / 8; q++) {
        const int r    = q * 8 + w;       // local row 0..63
        const int node = base + r;
        float4 acc = make_float4(0.f, 0.f, 0.f, 0.f);
        float inv = 0.f;
        if (node < n) {
            const int beg = g_off[node];
            const int end = g_off[node + 1];
            inv = 1.0f / (float)max(end - beg, 1);
            int e = beg;
            for (; e + 8 <= end; e += 8) {
                int idx[8];
                #pragma unroll
                for (int u = 0; u < 8; u++) idx[u] = __ldg(g_srcs + e + u);
                uint2 uv[8];
                #pragma unroll
                for (int u = 0; u < 8; u++)
                    uv[u] = __ldg((const uint2*)(g_sem16 + (size_t)idx[u] * HIDDEN) + lane);
                #pragma unroll
                for (int u = 0; u < 8; u++) {
                    float2 f0 = __half22float2(*(__half2*)&uv[u].x);
                    float2 f1 = __half22float2(*(__half2*)&uv[u].y);
                    acc.x += f0.x; acc.y += f0.y;
                    acc.z += f1.x; acc.w += f1.y;
                }
            }
            for (; e < end; e++) {
                int i0 = __ldg(g_srcs + e);
                uint2 u = __ldg((const uint2*)(g_sem16 + (size_t)i0 * HIDDEN) + lane);
                float2 f0 = __half22float2(*(__half2*)&u.x);
                float2 f1 = __half22float2(*(__half2*)&u.y);
                acc.x += f0.x; acc.y += f0.y;
                acc.z += f1.x; acc.w += f1.y;
            }
        }
        // Transposed, swizzled store; k = 4*lane + i, k>>2 = lane.
        const int ms = r ^ lane;
        sA[(4 * lane + 0) * NPB + ms] = acc.x * inv;
        sA[(4 * lane + 1) * NPB + ms] = acc.y * inv;
        sA[(4 * lane + 2) * NPB + ms] = acc.z * inv;
        sA[(4 * lane + 3) * NPB + ms] = acc.w * inv;
    }
    __syncthreads();

    // ---- GEMM phase (round-9 verified) ----
    const int n0 = w * 16;
    unsigned long long acc2[2][8];
    #pragma unroll
    for (int mi = 0; mi < 2; mi++)
        #pragma unroll
        for (int j = 0; j < 8; j++) acc2[mi][j] = 0ull;

    #pragma unroll 4
    for (int k = 0; k < HIDDEN; k++) {
        const int aoff = k * NPB + ((lane ^ (k >> 2)) & 63);
        unsigned long long a0 = pack_dup_f32x2(sA[aoff]);
        unsigned long long a1 = pack_dup_f32x2(sA[aoff + 32]);
        const unsigned long long* brow =
            (const unsigned long long*)(sB + k * HIDDEN + n0);
        #pragma unroll
        for (int j = 0; j < 8; j++) {
            unsigned long long b2 = brow[j];   // warp-uniform LDS.64
            fma_f32x2(acc2[0][j], a0, b2);
            fma_f32x2(acc2[1][j], a1, b2);
        }
    }

    // ---- Epilogue: exact GELU + vector stores ----
    #pragma unroll
    for (int mi = 0; mi < 2; mi++) {
        int row = base + lane + 32 * mi;
        if (row < n) {
            float* orow = out + (size_t)row * HIDDEN + n0;
            #pragma unroll
            for (int jj = 0; jj < 4; jj++) {
                float4 o;
                unpack_f32x2(acc2[mi][2 * jj],     o.x, o.y);
                unpack_f32x2(acc2[mi][2 * jj + 1], o.z, o.w);
                o.x = 0.5f * o.x * (1.0f + erff(o.x * 0.70710678118654752f));
                o.y = 0.5f * o.y * (1.0f + erff(o.y * 0.70710678118654752f));
                o.z = 0.5f * o.z * (1.0f + erff(o.z * 0.70710678118654752f));
                o.w = 0.5f * o.w * (1.0f + erff(o.w * 0.70710678118654752f));
                *(float4*)(orow + 4 * jj) = o;
            }
        }
    }
}

// ---------------------------------------------------------------------------
// kernel_launch: prep(probe+memset+fp16) -> hist -> scan -> place -> fused.
// All async on the default stream; graph-capturable; no allocations.
// Input order (metadata): semantics, attention_masks (unused), W, edge_index.
// ---------------------------------------------------------------------------
extern "C" void kernel_launch(void* const* d_in, const int* in_sizes, int n_in,
                              void* d_out, int out_size) {
    const float* sem = (const float*)d_in[0];
    const float* W   = (const float*)d_in[2];
    const void*  ei  = d_in[3];
    float* out = (float*)d_out;

    const int n       = in_sizes[0] / SEQ_STRIDE;   // 100000
    const int n_edges = in_sizes[3] / 2;            // 1600000

    prep_kernel<<<800, 512>>>(sem, (const long long*)ei, (long long)n, n);

    int eb = (n_edges + 511) / 512;
    hist_kernel<<<eb, 512>>>(ei, n_edges);
    scan_kernel<<<1, SCAN_THREADS>>>(n);
    place_kernel<<<eb, 512>>>(ei, n_edges);

    const int smem_bytes = (HIDDEN * HIDDEN + HIDDEN * NPB) * (int)sizeof(float);
    cudaFuncSetAttribute(agg_gemm_gelu_kernel,
                         cudaFuncAttributeMaxDynamicSharedMemorySize,
                         smem_bytes);
    int blocks = (n + NPB - 1) / NPB;
    agg_gemm_gelu_kernel<<<blocks, TPB, smem_bytes>>>(W, out, n);
}